// round 12
// baseline (speedup 1.0000x reference)
#include <cuda_runtime.h>

#define B_SZ 65536
#define D_SZ 512
#define V4_PER_ROW (D_SZ / 4)              // 128
#define NC 16
#define NBLOCKS 2048
#define NTHREADS 256
#define WARPS_PER_BLOCK (NTHREADS / 32)    // 8
#define ROWS_PER_WARP 4                    // 2048*8*4 = 65536
#define NPAIR (NC * (NC - 1) / 2)          // 120
#define PAIRS_PER_WARP (NPAIR / WARPS_PER_BLOCK)  // 15

// Volatile asm load: cannot be reordered or sunk by ptxas.
#define LDG128(v, p) \
    asm volatile("ld.global.nc.v4.f32 {%0,%1,%2,%3}, [%4];" \
        : "=f"((v).x), "=f"((v).y), "=f"((v).z), "=f"((v).w) : "l"(p))

__device__ float g_partials[NBLOCKS];
__device__ unsigned int g_ticket = 0;      // atomicInc wraps to 0 -> graph-replay safe

__global__ __launch_bounds__(NTHREADS, 6) void k_island_fused(
    const float4* __restrict__ x,
    const int* __restrict__ y,             // int32 (JAX x64 disabled)
    const float4* __restrict__ centers,
    float* __restrict__ out)
{
    __shared__ float4 sc[NC * V4_PER_ROW]; // 32 KB center cache (proven)
    __shared__ float ws[WARPS_PER_BLOCK];
    __shared__ float norms[NC];
    __shared__ float warp_pair[WARPS_PER_BLOCK];
    __shared__ unsigned int s_ticket;

    const int t = threadIdx.x;
    const int lane = t & 31;
    const int wid = t >> 5;

    #pragma unroll
    for (int i = 0; i < (NC * V4_PER_ROW) / NTHREADS; i++)
        sc[i * NTHREADS + t] = centers[i * NTHREADS + t];
    __syncthreads();

    // ---- Phase 1: R3 row body + asm-forced MLP4, at 6 CTA/SM ----
    const int gw = blockIdx.x * WARPS_PER_BLOCK + wid;

    float a0 = 0.f, a1 = 0.f, a2 = 0.f, a3 = 0.f;
    #pragma unroll
    for (int r = 0; r < ROWS_PER_WARP; r++) {
        const int row = gw * ROWS_PER_WARP + r;
        const int cls = __ldg(&y[row]) & 15;             // broadcast load
        const float4* xr = x + (size_t)row * V4_PER_ROW + lane;
        float4 x0, x1, x2, x3;
        LDG128(x0, xr);                                  // one base reg,
        LDG128(x1, xr + 32);                             // 512B immediate offsets
        LDG128(x2, xr + 64);
        LDG128(x3, xr + 96);
        const float4* cr = sc + (cls << 7) + lane;
        float4 c0 = cr[0];
        float4 c1 = cr[32];
        float4 c2 = cr[64];
        float4 c3 = cr[96];
        float d;
        d = x0.x - c0.x; a0 = fmaf(d, d, a0);
        d = x0.y - c0.y; a1 = fmaf(d, d, a1);
        d = x0.z - c0.z; a2 = fmaf(d, d, a2);
        d = x0.w - c0.w; a3 = fmaf(d, d, a3);
        d = x1.x - c1.x; a0 = fmaf(d, d, a0);
        d = x1.y - c1.y; a1 = fmaf(d, d, a1);
        d = x1.z - c1.z; a2 = fmaf(d, d, a2);
        d = x1.w - c1.w; a3 = fmaf(d, d, a3);
        d = x2.x - c2.x; a0 = fmaf(d, d, a0);
        d = x2.y - c2.y; a1 = fmaf(d, d, a1);
        d = x2.z - c2.z; a2 = fmaf(d, d, a2);
        d = x2.w - c2.w; a3 = fmaf(d, d, a3);
        d = x3.x - c3.x; a0 = fmaf(d, d, a0);
        d = x3.y - c3.y; a1 = fmaf(d, d, a1);
        d = x3.z - c3.z; a2 = fmaf(d, d, a2);
        d = x3.w - c3.w; a3 = fmaf(d, d, a3);
    }
    float acc = (a0 + a1) + (a2 + a3);

    #pragma unroll
    for (int o = 16; o > 0; o >>= 1)
        acc += __shfl_down_sync(0xffffffffu, acc, o);
    if (lane == 0) ws[wid] = acc;
    __syncthreads();
    if (t == 0) {
        float v = 0.f;
        #pragma unroll
        for (int w = 0; w < WARPS_PER_BLOCK; w++) v += ws[w];
        g_partials[blockIdx.x] = v;
        __threadfence();
        s_ticket = atomicInc(&g_ticket, NBLOCKS - 1);
    }
    __syncthreads();
    if (s_ticket != NBLOCKS - 1)
        return;                                       // not the last block

    // ---- Phase 2 (last block only): final reduce + island term ----
    float s = 0.0f;
    #pragma unroll
    for (int i = 0; i < NBLOCKS / NTHREADS; i++)
        s += g_partials[i * NTHREADS + t];
    #pragma unroll
    for (int o = 16; o > 0; o >>= 1)
        s += __shfl_down_sync(0xffffffffu, s, o);
    if (lane == 0) ws[wid] = s;

    // Norms: warp-per-2-rows (centers still resident in sc)
    #pragma unroll
    for (int r = 0; r < 2; r++) {
        const int row = wid * 2 + r;
        const float4* cr = sc + (row << 7);
        float ns = 0.0f;
        #pragma unroll
        for (int i = 0; i < 4; i++) {
            float4 v = cr[i * 32 + lane];
            ns += v.x * v.x + v.y * v.y + v.z * v.z + v.w * v.w;
        }
        #pragma unroll
        for (int o = 16; o > 0; o >>= 1)
            ns += __shfl_down_sync(0xffffffffu, ns, o);
        if (lane == 0) norms[row] = sqrtf(ns);
    }
    __syncthreads();

    // Pairs: 15 per warp, fixed order
    float psum = 0.0f;
    #pragma unroll
    for (int pp = 0; pp < PAIRS_PER_WARP; pp++) {
        const int p = wid * PAIRS_PER_WARP + pp;
        int j = 0, rem = p;
        while (rem >= NC - 1 - j) { rem -= NC - 1 - j; j++; }
        const int k = j + 1 + rem;
        const float4* cj = sc + (j << 7);
        const float4* ck = sc + (k << 7);
        float dot = 0.0f;
        #pragma unroll
        for (int i = 0; i < 4; i++) {
            float4 a = cj[i * 32 + lane];
            float4 b = ck[i * 32 + lane];
            dot += a.x * b.x + a.y * b.y + a.z * b.z + a.w * b.w;
        }
        #pragma unroll
        for (int o = 16; o > 0; o >>= 1)
            dot += __shfl_down_sync(0xffffffffu, dot, o);
        if (lane == 0)
            psum += dot / (norms[j] * norms[k] + 1e-9f) + 1.0f;
    }
    if (lane == 0) warp_pair[wid] = psum;
    __syncthreads();

    if (t == 0) {
        float total = 0.0f;
        float island = 0.0f;
        #pragma unroll
        for (int w = 0; w < WARPS_PER_BLOCK; w++) {
            total += ws[w];
            island += warp_pair[w];
        }
        // SCALE = 1, LAMDA = 1, LAMDA1 = 10
        float loss_center = 0.5f * total * (1.0f / (float)B_SZ);
        out[0] = loss_center + 10.0f * island;
    }
}

extern "C" void kernel_launch(void* const* d_in, const int* in_sizes, int n_in,
                              void* d_out, int out_size)
{
    // Identify inputs by element count (robust to ordering):
    //   output_features: 65536*512 = 33554432
    //   y_truth:         65536
    //   feature_centers: 16*512   = 8192
    const float4* x = nullptr;
    const int* y = nullptr;
    const float4* centers = nullptr;
    for (int i = 0; i < n_in; i++) {
        if (in_sizes[i] == 33554432)      x = (const float4*)d_in[i];
        else if (in_sizes[i] == 65536)    y = (const int*)d_in[i];
        else if (in_sizes[i] == 8192)     centers = (const float4*)d_in[i];
    }
    float* out = (float*)d_out;

    k_island_fused<<<NBLOCKS, NTHREADS>>>(x, y, centers, out);
}